// round 1
// baseline (speedup 1.0000x reference)
#include <cuda_runtime.h>
#include <math.h>

#define DIM    768
#define DEPTH  6
#define HEADS  12
#define DHEAD  64
#define INNER  768
#define MLPD   3072
#define BATCH  4
#define SEQ    2048
#define TOK    (BATCH*SEQ)      /* 8192 */
#define QKVD   (3*INNER)        /* 2304 */

// ---------------- scratch (device globals; no allocations) ----------------
__device__ float g_x  [(size_t)TOK*DIM];    // residual stream
__device__ float g_ln [(size_t)TOK*DIM];    // layernorm output
__device__ float g_qkv[(size_t)TOK*QKVD];   // fused qkv
__device__ float g_ctx[(size_t)TOK*DIM];    // attention context
__device__ float g_h  [(size_t)TOK*MLPD];   // mlp hidden

// ---------------- LayerNorm: one block per token, 256 threads -------------
__global__ void ln_kernel(const float* __restrict__ x, const float* __restrict__ g,
                          const float* __restrict__ b, float* __restrict__ y)
{
    int t = blockIdx.x;
    const float* xp = x + (size_t)t * DIM;
    float*       yp = y + (size_t)t * DIM;

    float v[3];
    float s1 = 0.f, s2 = 0.f;
#pragma unroll
    for (int i = 0; i < 3; i++) {
        v[i] = xp[threadIdx.x + i * 256];
        s1 += v[i];
        s2 += v[i] * v[i];
    }
#pragma unroll
    for (int o = 16; o > 0; o >>= 1) {
        s1 += __shfl_xor_sync(0xffffffffu, s1, o);
        s2 += __shfl_xor_sync(0xffffffffu, s2, o);
    }
    __shared__ float r1[8], r2[8];
    if ((threadIdx.x & 31) == 0) { r1[threadIdx.x >> 5] = s1; r2[threadIdx.x >> 5] = s2; }
    __syncthreads();
    s1 = 0.f; s2 = 0.f;
#pragma unroll
    for (int i = 0; i < 8; i++) { s1 += r1[i]; s2 += r2[i]; }

    float mu  = s1 * (1.f / DIM);
    float var = s2 * (1.f / DIM) - mu * mu;
    float rs  = rsqrtf(var + 1e-5f);
#pragma unroll
    for (int i = 0; i < 3; i++) {
        int d = threadIdx.x + i * 256;
        yp[d] = (v[i] - mu) * rs * g[d] + b[d];
    }
}

// ---------------- SGEMM: C = A[M,K] @ B[K,N] (+bias)(+gelu)(+res) ---------
// BM=BN=128, BK=16, 256 threads, 8x8 micro-tile, register prefetch.
template<bool BIAS, bool GELU_, bool RES>
__global__ void __launch_bounds__(256, 2)
sgemm_kernel(const float* __restrict__ A, const float* __restrict__ B,
             const float* __restrict__ bias, const float* __restrict__ res,
             float* __restrict__ C, int M, int N, int K)
{
    constexpr int BM = 128, BN = 128, BK = 16;
    __shared__ float As[BK][BM];
    __shared__ float Bs[BK][BN];

    const int tid = threadIdx.x;
    const int bm  = blockIdx.y, bn = blockIdx.x;
    const int tx  = tid & 15, ty = tid >> 4;

    const int arow = tid >> 1;            // 0..127
    const int acol = (tid & 1) * 8;       // 0 or 8
    const int brow = tid >> 4;            // 0..15
    const int bcol = (tid & 15) * 8;      // 0..120

    const float* Ap = A + ((size_t)(bm * BM + arow)) * K + acol;
    const float* Bp = B + ((size_t)brow) * N + (size_t)bn * BN + bcol;

    float4 ar0, ar1, br0, br1;
    float  acc[8][8];
#pragma unroll
    for (int i = 0; i < 8; i++)
#pragma unroll
        for (int j = 0; j < 8; j++) acc[i][j] = 0.f;

    // prologue: tile 0
    ar0 = *(const float4*)(Ap);
    ar1 = *(const float4*)(Ap + 4);
    br0 = *(const float4*)(Bp);
    br1 = *(const float4*)(Bp + 4);

    const int nkt = K / BK;
    for (int kt = 0; kt < nkt; kt++) {
        // store current tile to smem
        As[acol + 0][arow] = ar0.x; As[acol + 1][arow] = ar0.y;
        As[acol + 2][arow] = ar0.z; As[acol + 3][arow] = ar0.w;
        As[acol + 4][arow] = ar1.x; As[acol + 5][arow] = ar1.y;
        As[acol + 6][arow] = ar1.z; As[acol + 7][arow] = ar1.w;
        *(float4*)&Bs[brow][bcol]     = br0;
        *(float4*)&Bs[brow][bcol + 4] = br1;
        __syncthreads();

        // prefetch next tile
        if (kt + 1 < nkt) {
            const float* ap = Ap + (kt + 1) * BK;
            const float* bp = Bp + (size_t)(kt + 1) * BK * N;
            ar0 = *(const float4*)(ap);
            ar1 = *(const float4*)(ap + 4);
            br0 = *(const float4*)(bp);
            br1 = *(const float4*)(bp + 4);
        }

        // compute on smem tile
#pragma unroll
        for (int kk = 0; kk < BK; kk++) {
            float a[8], b[8];
            *(float4*)&a[0] = *(const float4*)&As[kk][ty * 8];
            *(float4*)&a[4] = *(const float4*)&As[kk][ty * 8 + 4];
            *(float4*)&b[0] = *(const float4*)&Bs[kk][tx * 8];
            *(float4*)&b[4] = *(const float4*)&Bs[kk][tx * 8 + 4];
#pragma unroll
            for (int i = 0; i < 8; i++)
#pragma unroll
                for (int j = 0; j < 8; j++)
                    acc[i][j] += a[i] * b[j];
        }
        __syncthreads();
    }

    // epilogue
    const int row0 = bm * BM + ty * 8;
    const int col0 = bn * BN + tx * 8;
#pragma unroll
    for (int i = 0; i < 8; i++) {
        const int row = row0 + i;
        float out[8];
#pragma unroll
        for (int j = 0; j < 8; j++) {
            float v = acc[i][j];
            const int col = col0 + j;
            if (BIAS)  v += bias[col];
            if (GELU_) v = 0.5f * v * (1.f + erff(v * 0.70710678118654752f));
            if (RES)   v += res[(size_t)row * N + col];
            out[j] = v;
        }
        *(float4*)&C[(size_t)row * N + col0]     = *(float4*)&out[0];
        *(float4*)&C[(size_t)row * N + col0 + 4] = *(float4*)&out[4];
    }
}

// ---------------- Flash attention (fp32, online softmax) ------------------
// One thread per query; 16-key smem tiles; q/o in registers.
__global__ void __launch_bounds__(256, 1)
attn_kernel(const float* __restrict__ qkv, float* __restrict__ ctx)
{
    const int b  = blockIdx.z;
    const int h  = blockIdx.y;
    const int q  = blockIdx.x * 256 + threadIdx.x;   // query index in sequence

    const float scale = 0.125f;                       // 1/sqrt(64)
    const float* qp = qkv + ((size_t)(b * SEQ + q)) * QKVD + h * DHEAD;

    float qv[DHEAD];
#pragma unroll
    for (int d = 0; d < DHEAD; d += 4) {
        float4 t = *(const float4*)(qp + d);
        qv[d] = t.x * scale; qv[d+1] = t.y * scale; qv[d+2] = t.z * scale; qv[d+3] = t.w * scale;
    }

    float o[DHEAD];
#pragma unroll
    for (int d = 0; d < DHEAD; d++) o[d] = 0.f;
    float m = -1e30f, l = 0.f;

    __shared__ float Ks[16][DHEAD];
    __shared__ float Vs[16][DHEAD];

    for (int k0 = 0; k0 < SEQ; k0 += 16) {
        __syncthreads();
        {   // cooperative load: 16x64 floats each = 256 float4 -> 1 per thread
            const int r = threadIdx.x >> 4;
            const int c = (threadIdx.x & 15) * 4;
            const size_t base = ((size_t)(b * SEQ + k0 + r)) * QKVD + h * DHEAD + c;
            *(float4*)&Ks[r][c] = *(const float4*)(qkv + base + INNER);
            *(float4*)&Vs[r][c] = *(const float4*)(qkv + base + 2 * INNER);
        }
        __syncthreads();

        float s[16];
#pragma unroll
        for (int j = 0; j < 16; j++) {
            float acc = 0.f;
#pragma unroll
            for (int d = 0; d < DHEAD; d += 4) {
                float4 kv = *(const float4*)&Ks[j][d];
                acc += qv[d] * kv.x + qv[d+1] * kv.y + qv[d+2] * kv.z + qv[d+3] * kv.w;
            }
            s[j] = acc;
        }
        float mt = m;
#pragma unroll
        for (int j = 0; j < 16; j++) mt = fmaxf(mt, s[j]);
        const float corr = __expf(m - mt);
        m = mt;
        l *= corr;
#pragma unroll
        for (int d = 0; d < DHEAD; d++) o[d] *= corr;
#pragma unroll
        for (int j = 0; j < 16; j++) {
            const float p = __expf(s[j] - m);
            l += p;
#pragma unroll
            for (int d = 0; d < DHEAD; d += 4) {
                float4 vv = *(const float4*)&Vs[j][d];
                o[d]   += p * vv.x; o[d+1] += p * vv.y;
                o[d+2] += p * vv.z; o[d+3] += p * vv.w;
            }
        }
    }

    const float inv = 1.f / l;
    float* op = ctx + ((size_t)(b * SEQ + q)) * DIM + h * DHEAD;
#pragma unroll
    for (int d = 0; d < DHEAD; d += 4) {
        float4 t;
        t.x = o[d] * inv; t.y = o[d+1] * inv; t.z = o[d+2] * inv; t.w = o[d+3] * inv;
        *(float4*)(op + d) = t;
    }
}

// ---------------- driver ---------------------------------------------------
extern "C" void kernel_launch(void* const* d_in, const int* in_sizes, int n_in,
                              void* d_out, int out_size)
{
    const float* x    = (const float*)d_in[0];
    const float* ln1g = (const float*)d_in[1];
    const float* ln1b = (const float*)d_in[2];
    const float* wqkv = (const float*)d_in[3];
    const float* wout = (const float*)d_in[4];
    const float* ln2g = (const float*)d_in[5];
    const float* ln2b = (const float*)d_in[6];
    const float* w1   = (const float*)d_in[7];
    const float* b1   = (const float*)d_in[8];
    const float* w2   = (const float*)d_in[9];
    const float* b2   = (const float*)d_in[10];
    const float* fng  = (const float*)d_in[11];
    const float* fnb  = (const float*)d_in[12];

    float *px, *pln, *pqkv, *pctx, *ph;
    cudaGetSymbolAddress((void**)&px,   g_x);
    cudaGetSymbolAddress((void**)&pln,  g_ln);
    cudaGetSymbolAddress((void**)&pqkv, g_qkv);
    cudaGetSymbolAddress((void**)&pctx, g_ctx);
    cudaGetSymbolAddress((void**)&ph,   g_h);

    cudaMemcpyAsync(px, x, sizeof(float) * (size_t)TOK * DIM,
                    cudaMemcpyDeviceToDevice, 0);

    const dim3 blk(256);
    for (int i = 0; i < DEPTH; i++) {
        // ---- attention block ----
        ln_kernel<<<TOK, blk>>>(px, ln1g + i * DIM, ln1b + i * DIM, pln);
        sgemm_kernel<false, false, false>
            <<<dim3(QKVD / 128, TOK / 128), blk>>>(
                pln, wqkv + (size_t)i * DIM * QKVD, nullptr, nullptr,
                pqkv, TOK, QKVD, DIM);
        attn_kernel<<<dim3(SEQ / 256, HEADS, BATCH), blk>>>(pqkv, pctx);
        sgemm_kernel<false, false, true>
            <<<dim3(DIM / 128, TOK / 128), blk>>>(
                pctx, wout + (size_t)i * INNER * DIM, nullptr, px,
                px, TOK, DIM, INNER);

        // ---- mlp block ----
        ln_kernel<<<TOK, blk>>>(px, ln2g + i * DIM, ln2b + i * DIM, pln);
        sgemm_kernel<true, true, false>
            <<<dim3(MLPD / 128, TOK / 128), blk>>>(
                pln, w1 + (size_t)i * DIM * MLPD, b1 + (size_t)i * MLPD, nullptr,
                ph, TOK, MLPD, DIM);
        sgemm_kernel<true, false, true>
            <<<dim3(DIM / 128, TOK / 128), blk>>>(
                ph, w2 + (size_t)i * MLPD * DIM, b2 + (size_t)i * DIM, px,
                px, TOK, DIM, MLPD);
    }

    ln_kernel<<<TOK, blk>>>(px, fng, fnb, (float*)d_out);
}

// round 3
// speedup vs baseline: 1.4928x; 1.4928x over previous
#include <cuda_runtime.h>
#include <cuda_bf16.h>
#include <math.h>
#include <stdint.h>

#define DIM    768
#define DEPTH  6
#define HEADS  12
#define DHEAD  64
#define INNER  768
#define MLPD   3072
#define BATCH  4
#define SEQ    2048
#define TOK    (BATCH*SEQ)      /* 8192 */
#define QKVD   (3*INNER)        /* 2304 */

// ---------------- scratch (device globals; no allocations) ----------------
__device__ float g_x  [(size_t)TOK*DIM];     // residual stream fp32
__device__ float g_qkv[(size_t)TOK*QKVD];    // fused qkv fp32
__device__ __nv_bfloat16 g_lnh[(size_t)TOK*DIM];
__device__ __nv_bfloat16 g_lnl[(size_t)TOK*DIM];
__device__ __nv_bfloat16 g_cth[(size_t)TOK*DIM];
__device__ __nv_bfloat16 g_ctl[(size_t)TOK*DIM];
__device__ __nv_bfloat16 g_hh [(size_t)TOK*MLPD];
__device__ __nv_bfloat16 g_hl [(size_t)TOK*MLPD];
// transposed bf16 hi/lo weights [layer][N][K]
__device__ __nv_bfloat16 g_wqkvt_h[(size_t)DEPTH*QKVD*DIM];
__device__ __nv_bfloat16 g_wqkvt_l[(size_t)DEPTH*QKVD*DIM];
__device__ __nv_bfloat16 g_woutt_h[(size_t)DEPTH*DIM*INNER];
__device__ __nv_bfloat16 g_woutt_l[(size_t)DEPTH*DIM*INNER];
__device__ __nv_bfloat16 g_w1t_h [(size_t)DEPTH*MLPD*DIM];
__device__ __nv_bfloat16 g_w1t_l [(size_t)DEPTH*MLPD*DIM];
__device__ __nv_bfloat16 g_w2t_h [(size_t)DEPTH*DIM*MLPD];
__device__ __nv_bfloat16 g_w2t_l [(size_t)DEPTH*DIM*MLPD];

// ====================== PTX helpers =======================================
__device__ __forceinline__ uint32_t smem_u32(const void* p){
    uint32_t a;
    asm("{ .reg .u64 t; cvta.to.shared.u64 t, %1; cvt.u32.u64 %0, t; }"
        : "=r"(a) : "l"(p));
    return a;
}
__device__ __forceinline__ void cp16(uint32_t s, const void* g){
    asm volatile("cp.async.cg.shared.global [%0], [%1], 16;" :: "r"(s), "l"(g));
}
#define CP_COMMIT() asm volatile("cp.async.commit_group;" ::: "memory")
#define CP_WAIT1()  asm volatile("cp.async.wait_group 1;" ::: "memory")
#define CP_WAIT0()  asm volatile("cp.async.wait_group 0;" ::: "memory")

__device__ __forceinline__ void ldmx4(uint32_t addr, uint32_t& r0, uint32_t& r1,
                                      uint32_t& r2, uint32_t& r3){
    asm volatile("ldmatrix.sync.aligned.m8n8.x4.shared.b16 {%0,%1,%2,%3}, [%4];"
        : "=r"(r0), "=r"(r1), "=r"(r2), "=r"(r3) : "r"(addr));
}
__device__ __forceinline__ void mma16816(float* c, const uint32_t* a,
                                         uint32_t b0, uint32_t b1){
    asm volatile(
        "mma.sync.aligned.m16n8k16.row.col.f32.bf16.bf16.f32 "
        "{%0,%1,%2,%3}, {%4,%5,%6,%7}, {%8,%9}, {%0,%1,%2,%3};"
        : "+f"(c[0]), "+f"(c[1]), "+f"(c[2]), "+f"(c[3])
        : "r"(a[0]), "r"(a[1]), "r"(a[2]), "r"(a[3]), "r"(b0), "r"(b1));
}

// ====================== weight transpose + bf16 split ======================
// W[z][K][N] fp32 -> Wh/Wl[z][N][K] bf16
__global__ void transpose_cvt(const float* __restrict__ W,
                              __nv_bfloat16* __restrict__ Wh,
                              __nv_bfloat16* __restrict__ Wl, int K, int N)
{
    __shared__ float tile[32][33];
    const size_t off = (size_t)blockIdx.z * K * N;
    const int n0 = blockIdx.x * 32, k0 = blockIdx.y * 32;
    const int tx = threadIdx.x, ty = threadIdx.y;
#pragma unroll
    for (int i = 0; i < 32; i += 8)
        tile[ty + i][tx] = W[off + (size_t)(k0 + ty + i) * N + n0 + tx];
    __syncthreads();
#pragma unroll
    for (int i = 0; i < 32; i += 8) {
        float v = tile[tx][ty + i];
        __nv_bfloat16 h = __float2bfloat16(v);
        __nv_bfloat16 l = __float2bfloat16(v - __bfloat162float(h));
        size_t oidx = off + (size_t)(n0 + ty + i) * K + k0 + tx;
        Wh[oidx] = h; Wl[oidx] = l;
    }
}

// ====================== LayerNorm ==========================================
template<bool BF16OUT>
__global__ void ln_kernel(const float* __restrict__ x, const float* __restrict__ g,
                          const float* __restrict__ b, float* __restrict__ y,
                          __nv_bfloat16* __restrict__ yh, __nv_bfloat16* __restrict__ yl)
{
    int t = blockIdx.x;
    const float* xp = x + (size_t)t * DIM;

    float v[3];
    float s1 = 0.f, s2 = 0.f;
#pragma unroll
    for (int i = 0; i < 3; i++) {
        v[i] = xp[threadIdx.x + i * 256];
        s1 += v[i]; s2 += v[i] * v[i];
    }
#pragma unroll
    for (int o = 16; o > 0; o >>= 1) {
        s1 += __shfl_xor_sync(0xffffffffu, s1, o);
        s2 += __shfl_xor_sync(0xffffffffu, s2, o);
    }
    __shared__ float r1[8], r2[8];
    if ((threadIdx.x & 31) == 0) { r1[threadIdx.x >> 5] = s1; r2[threadIdx.x >> 5] = s2; }
    __syncthreads();
    s1 = 0.f; s2 = 0.f;
#pragma unroll
    for (int i = 0; i < 8; i++) { s1 += r1[i]; s2 += r2[i]; }

    float mu  = s1 * (1.f / DIM);
    float var = s2 * (1.f / DIM) - mu * mu;
    float rs  = rsqrtf(var + 1e-5f);
#pragma unroll
    for (int i = 0; i < 3; i++) {
        int d = threadIdx.x + i * 256;
        float yy = (v[i] - mu) * rs * g[d] + b[d];
        if (BF16OUT) {
            __nv_bfloat16 h = __float2bfloat16(yy);
            yh[(size_t)t * DIM + d] = h;
            yl[(size_t)t * DIM + d] = __float2bfloat16(yy - __bfloat162float(h));
        } else {
            y[(size_t)t * DIM + d] = yy;
        }
    }
}

// ====================== HMMA split-bf16 GEMM ===============================
// C[M,N] = A[M,K] @ Bt[N,K]^T, A/Bt in bf16 hi/lo pairs, fp32 accum.
// CTA 128x128, BK=32, 3-stage cp.async pipeline.
// EPI: 0 = fp32 out; 1 = +bias,gelu,bf16 hi/lo out; 2 = +bias += res; 3 = += res.
template<int EPI>
__global__ void __launch_bounds__(256, 1)
gemm_mma(const __nv_bfloat16* __restrict__ Ah, const __nv_bfloat16* __restrict__ Al,
         const __nv_bfloat16* __restrict__ Bh, const __nv_bfloat16* __restrict__ Bl,
         const float* __restrict__ bias, float* __restrict__ xres,
         float* __restrict__ Cf, __nv_bfloat16* __restrict__ Ch,
         __nv_bfloat16* __restrict__ Cl, int M, int N, int K)
{
    extern __shared__ char smem[];
    const uint32_t sb0 = smem_u32(smem);
    const int tid  = threadIdx.x;
    const int lane = tid & 31, warp = tid >> 5;
    const int wm = warp >> 1, wn = warp & 1;
    const int bn = blockIdx.x, bm = blockIdx.y;
    const int nkt = K >> 5;

    // stage layout: [A_hi 8K][A_lo 8K][B_hi 8K][B_lo 8K] = 32KB
    auto load_stage = [&](int kt, int st){
        const uint32_t base = sb0 + st * 32768u;
        const size_t kof = (size_t)kt * 32;
#pragma unroll
        for (int i = 0; i < 2; i++) {
            const int idx = tid + i * 256;
            const int row = idx >> 2, c = idx & 3;
            const uint32_t so = (uint32_t)(row * 64 + ((c ^ ((row >> 1) & 3)) << 4));
            const size_t ga = (size_t)(bm * 128 + row) * K + kof + c * 8;
            const size_t gb = (size_t)(bn * 128 + row) * K + kof + c * 8;
            cp16(base + so,          Ah + ga);
            cp16(base + 8192u + so,  Al + ga);
            cp16(base + 16384u + so, Bh + gb);
            cp16(base + 24576u + so, Bl + gb);
        }
    };

    float acc[2][8][4];
#pragma unroll
    for (int mt = 0; mt < 2; mt++)
#pragma unroll
        for (int nt = 0; nt < 8; nt++)
#pragma unroll
            for (int q = 0; q < 4; q++) acc[mt][nt][q] = 0.f;

    load_stage(0, 0); CP_COMMIT();
    load_stage(1, 1); CP_COMMIT();

    // ldmatrix per-lane address components
    const int arow = wm * 32 + (lane & 15);          // + mt*16
    const int acs  = lane >> 4;                      // A chunk sub
    const int brow = wn * 64 + (lane & 7) + ((lane >> 4) << 3);   // + bt*16
    const int bcs  = (lane >> 3) & 1;                // B chunk sub

    for (int kt = 0; kt < nkt; kt++) {
        if (kt == nkt - 1) { CP_WAIT0(); } else { CP_WAIT1(); }
        __syncthreads();
        if (kt + 2 < nkt) { load_stage(kt + 2, (kt + 2) % 3); CP_COMMIT(); }

        const uint32_t base = sb0 + (uint32_t)(kt % 3) * 32768u;
#pragma unroll
        for (int ks = 0; ks < 2; ks++) {
            uint32_t ah[2][4], al_[2][4];
#pragma unroll
            for (int mt = 0; mt < 2; mt++) {
                const int r = arow + mt * 16;
                const int c = ks * 2 + acs;
                const uint32_t off = (uint32_t)(r * 64 + ((c ^ ((r >> 1) & 3)) << 4));
                ldmx4(base + off,         ah[mt][0],  ah[mt][1],  ah[mt][2],  ah[mt][3]);
                ldmx4(base + 8192u + off, al_[mt][0], al_[mt][1], al_[mt][2], al_[mt][3]);
            }
            uint32_t bh[4][4], bl_[4][4];
#pragma unroll
            for (int bt = 0; bt < 4; bt++) {
                const int r = brow + bt * 16;
                const int c = ks * 2 + bcs;
                const uint32_t off = (uint32_t)(r * 64 + ((c ^ ((r >> 1) & 3)) << 4));
                ldmx4(base + 16384u + off, bh[bt][0],  bh[bt][1],  bh[bt][2],  bh[bt][3]);
                ldmx4(base + 24576u + off, bl_[bt][0], bl_[bt][1], bl_[bt][2], bl_[bt][3]);
            }
#pragma unroll
            for (int mt = 0; mt < 2; mt++)
#pragma unroll
                for (int nt = 0; nt < 8; nt++) {
                    const int bt = nt >> 1, o = (nt & 1) * 2;
                    mma16816(acc[mt][nt], ah[mt],  bh[bt][o],  bh[bt][o + 1]);
                    mma16816(acc[mt][nt], ah[mt],  bl_[bt][o], bl_[bt][o + 1]);
                    mma16816(acc[mt][nt], al_[mt], bh[bt][o],  bh[bt][o + 1]);
                }
        }
        __syncthreads();
    }

    // ---------------- epilogue ----------------
    const int rbase = bm * 128 + wm * 32 + (lane >> 2);
    const int cbase = bn * 128 + wn * 64 + (lane & 3) * 2;
#pragma unroll
    for (int mt = 0; mt < 2; mt++) {
#pragma unroll
        for (int nt = 0; nt < 8; nt++) {
            const int gcol = cbase + nt * 8;
#pragma unroll
            for (int h = 0; h < 2; h++) {                 // h=0: rows, h=1: rows+8
                const int grow = rbase + mt * 16 + h * 8;
                float v0 = acc[mt][nt][2 * h], v1 = acc[mt][nt][2 * h + 1];
                const size_t oidx = (size_t)grow * N + gcol;
                if (EPI == 0) {
                    *reinterpret_cast<float2*>(Cf + oidx) = make_float2(v0, v1);
                } else if (EPI == 1) {
                    v0 += bias[gcol];     v1 += bias[gcol + 1];
                    v0 = 0.5f * v0 * (1.f + erff(v0 * 0.70710678118654752f));
                    v1 = 0.5f * v1 * (1.f + erff(v1 * 0.70710678118654752f));
                    __nv_bfloat16 h0 = __float2bfloat16(v0), h1 = __float2bfloat16(v1);
                    __nv_bfloat16 l0 = __float2bfloat16(v0 - __bfloat162float(h0));
                    __nv_bfloat16 l1 = __float2bfloat16(v1 - __bfloat162float(h1));
                    *reinterpret_cast<uint32_t*>(Ch + oidx) =
                        (uint32_t)__bfloat16_as_ushort(h0) |
                        ((uint32_t)__bfloat16_as_ushort(h1) << 16);
                    *reinterpret_cast<uint32_t*>(Cl + oidx) =
                        (uint32_t)__bfloat16_as_ushort(l0) |
                        ((uint32_t)__bfloat16_as_ushort(l1) << 16);
                } else {
                    float2 xv = *reinterpret_cast<const float2*>(xres + oidx);
                    if (EPI == 2) { v0 += bias[gcol]; v1 += bias[gcol + 1]; }
                    xv.x += v0; xv.y += v1;
                    *reinterpret_cast<float2*>(xres + oidx) = xv;
                }
            }
        }
    }
}

// ====================== Flash attention (fp32) + bf16 split out ============
__global__ void __launch_bounds__(256, 1)
attn_kernel(const float* __restrict__ qkv, __nv_bfloat16* __restrict__ ch,
            __nv_bfloat16* __restrict__ cl)
{
    const int b = blockIdx.z;
    const int h = blockIdx.y;
    const int q = blockIdx.x * 256 + threadIdx.x;

    const float scale = 0.125f;
    const float* qp = qkv + ((size_t)(b * SEQ + q)) * QKVD + h * DHEAD;

    float qv[DHEAD];
#pragma unroll
    for (int d = 0; d < DHEAD; d += 4) {
        float4 t = *(const float4*)(qp + d);
        qv[d] = t.x * scale; qv[d+1] = t.y * scale;
        qv[d+2] = t.z * scale; qv[d+3] = t.w * scale;
    }

    float o[DHEAD];
#pragma unroll
    for (int d = 0; d < DHEAD; d++) o[d] = 0.f;
    float m = -1e30f, l = 0.f;

    __shared__ float Ks[16][DHEAD];
    __shared__ float Vs[16][DHEAD];

    for (int k0 = 0; k0 < SEQ; k0 += 16) {
        __syncthreads();
        {
            const int r = threadIdx.x >> 4;
            const int c = (threadIdx.x & 15) * 4;
            const size_t base = ((size_t)(b * SEQ + k0 + r)) * QKVD + h * DHEAD + c;
            *(float4*)&Ks[r][c] = *(const float4*)(qkv + base + INNER);
            *(float4*)&Vs[r][c] = *(const float4*)(qkv + base + 2 * INNER);
        }
        __syncthreads();

        float s[16];
#pragma unroll
        for (int j = 0; j < 16; j++) {
            float acc = 0.f;
#pragma unroll
            for (int d = 0; d < DHEAD; d += 4) {
                float4 kv = *(const float4*)&Ks[j][d];
                acc += qv[d] * kv.x + qv[d+1] * kv.y + qv[d+2] * kv.z + qv[d+3] * kv.w;
            }
            s[j] = acc;
        }
        float mt = m;
#pragma unroll
        for (int j = 0; j < 16; j++) mt = fmaxf(mt, s[j]);
        const float corr = __expf(m - mt);
        m = mt;
        l *= corr;
#pragma unroll
        for (int d = 0; d < DHEAD; d++) o[d] *= corr;
#pragma unroll
        for (int j = 0; j < 16; j++) {
            const float p = __expf(s[j] - m);
            l += p;
#pragma unroll
            for (int d = 0; d < DHEAD; d += 4) {
                float4 vv = *(const float4*)&Vs[j][d];
                o[d]   += p * vv.x; o[d+1] += p * vv.y;
                o[d+2] += p * vv.z; o[d+3] += p * vv.w;
            }
        }
    }

    const float inv = 1.f / l;
    const size_t obase = ((size_t)(b * SEQ + q)) * DIM + h * DHEAD;
#pragma unroll
    for (int d = 0; d < DHEAD; d += 2) {
        float v0 = o[d] * inv, v1 = o[d+1] * inv;
        __nv_bfloat16 h0 = __float2bfloat16(v0), h1 = __float2bfloat16(v1);
        __nv_bfloat16 l0 = __float2bfloat16(v0 - __bfloat162float(h0));
        __nv_bfloat16 l1 = __float2bfloat16(v1 - __bfloat162float(h1));
        *reinterpret_cast<uint32_t*>(ch + obase + d) =
            (uint32_t)__bfloat16_as_ushort(h0) | ((uint32_t)__bfloat16_as_ushort(h1) << 16);
        *reinterpret_cast<uint32_t*>(cl + obase + d) =
            (uint32_t)__bfloat16_as_ushort(l0) | ((uint32_t)__bfloat16_as_ushort(l1) << 16);
    }
}

// ====================== driver =============================================
#define GEMM_SMEM (3 * 32768)

extern "C" void kernel_launch(void* const* d_in, const int* in_sizes, int n_in,
                              void* d_out, int out_size)
{
    const float* x    = (const float*)d_in[0];
    const float* ln1g = (const float*)d_in[1];
    const float* ln1b = (const float*)d_in[2];
    const float* wqkv = (const float*)d_in[3];
    const float* wout = (const float*)d_in[4];
    const float* ln2g = (const float*)d_in[5];
    const float* ln2b = (const float*)d_in[6];
    const float* w1   = (const float*)d_in[7];
    const float* b1   = (const float*)d_in[8];
    const float* w2   = (const float*)d_in[9];
    const float* b2   = (const float*)d_in[10];
    const float* fng  = (const float*)d_in[11];
    const float* fnb  = (const float*)d_in[12];

    float *px, *pqkv;
    __nv_bfloat16 *plnh, *plnl, *pcth, *pctl, *phh, *phl;
    __nv_bfloat16 *qkvh, *qkvl, *outh, *outl, *w1h, *w1l, *w2h, *w2l;
    cudaGetSymbolAddress((void**)&px,   g_x);
    cudaGetSymbolAddress((void**)&pqkv, g_qkv);
    cudaGetSymbolAddress((void**)&plnh, g_lnh);
    cudaGetSymbolAddress((void**)&plnl, g_lnl);
    cudaGetSymbolAddress((void**)&pcth, g_cth);
    cudaGetSymbolAddress((void**)&pctl, g_ctl);
    cudaGetSymbolAddress((void**)&phh,  g_hh);
    cudaGetSymbolAddress((void**)&phl,  g_hl);
    cudaGetSymbolAddress((void**)&qkvh, g_wqkvt_h);
    cudaGetSymbolAddress((void**)&qkvl, g_wqkvt_l);
    cudaGetSymbolAddress((void**)&outh, g_woutt_h);
    cudaGetSymbolAddress((void**)&outl, g_woutt_l);
    cudaGetSymbolAddress((void**)&w1h,  g_w1t_h);
    cudaGetSymbolAddress((void**)&w1l,  g_w1t_l);
    cudaGetSymbolAddress((void**)&w2h,  g_w2t_h);
    cudaGetSymbolAddress((void**)&w2l,  g_w2t_l);

    cudaFuncSetAttribute(gemm_mma<0>, cudaFuncAttributeMaxDynamicSharedMemorySize, GEMM_SMEM);
    cudaFuncSetAttribute(gemm_mma<1>, cudaFuncAttributeMaxDynamicSharedMemorySize, GEMM_SMEM);
    cudaFuncSetAttribute(gemm_mma<2>, cudaFuncAttributeMaxDynamicSharedMemorySize, GEMM_SMEM);
    cudaFuncSetAttribute(gemm_mma<3>, cudaFuncAttributeMaxDynamicSharedMemorySize, GEMM_SMEM);

    // weight prep: transpose + split to bf16 hi/lo
    {
        dim3 tblk(32, 8);
        transpose_cvt<<<dim3(QKVD/32, DIM/32, DEPTH), tblk>>>(wqkv, qkvh, qkvl, DIM, QKVD);
        transpose_cvt<<<dim3(DIM/32, INNER/32, DEPTH), tblk>>>(wout, outh, outl, INNER, DIM);
        transpose_cvt<<<dim3(MLPD/32, DIM/32, DEPTH), tblk>>>(w1, w1h, w1l, DIM, MLPD);
        transpose_cvt<<<dim3(DIM/32, MLPD/32, DEPTH), tblk>>>(w2, w2h, w2l, MLPD, DIM);
    }

    cudaMemcpyAsync(px, x, sizeof(float) * (size_t)TOK * DIM,
                    cudaMemcpyDeviceToDevice, 0);

    const dim3 blk256(256);
    for (int i = 0; i < DEPTH; i++) {
        // ---- attention block ----
        ln_kernel<true><<<TOK, blk256>>>(px, ln1g + i*DIM, ln1b + i*DIM,
                                         nullptr, plnh, plnl);
        gemm_mma<0><<<dim3(QKVD/128, TOK/128), blk256, GEMM_SMEM>>>(
            plnh, plnl,
            qkvh + (size_t)i*QKVD*DIM, qkvl + (size_t)i*QKVD*DIM,
            nullptr, nullptr, pqkv, nullptr, nullptr, TOK, QKVD, DIM);
        attn_kernel<<<dim3(SEQ/256, HEADS, BATCH), blk256>>>(pqkv, pcth, pctl);
        gemm_mma<3><<<dim3(DIM/128, TOK/128), blk256, GEMM_SMEM>>>(
            pcth, pctl,
            outh + (size_t)i*DIM*INNER, outl + (size_t)i*DIM*INNER,
            nullptr, px, nullptr, nullptr, nullptr, TOK, DIM, INNER);

        // ---- mlp block ----
        ln_kernel<true><<<TOK, blk256>>>(px, ln2g + i*DIM, ln2b + i*DIM,
                                         nullptr, plnh, plnl);
        gemm_mma<1><<<dim3(MLPD/128, TOK/128), blk256, GEMM_SMEM>>>(
            plnh, plnl,
            w1h + (size_t)i*MLPD*DIM, w1l + (size_t)i*MLPD*DIM,
            b1 + (size_t)i*MLPD, nullptr, nullptr, phh, phl, TOK, MLPD, DIM);
        gemm_mma<2><<<dim3(DIM/128, TOK/128), blk256, GEMM_SMEM>>>(
            phh, phl,
            w2h + (size_t)i*DIM*MLPD, w2l + (size_t)i*DIM*MLPD,
            b2 + (size_t)i*DIM, px, nullptr, nullptr, nullptr, TOK, DIM, MLPD);
    }

    ln_kernel<false><<<TOK, blk256>>>(px, fng, fnb, (float*)d_out, nullptr, nullptr);
}

// round 4
// speedup vs baseline: 2.8066x; 1.8800x over previous
#include <cuda_runtime.h>
#include <cuda_bf16.h>
#include <math.h>
#include <stdint.h>

#define DIM    768
#define DEPTH  6
#define HEADS  12
#define DHEAD  64
#define INNER  768
#define MLPD   3072
#define BATCH  4
#define SEQ    2048
#define TOK    (BATCH*SEQ)      /* 8192 */
#define QKVD   (3*INNER)        /* 2304 */
#define QSCALE 0.18033688011112042f   /* 0.125 * log2(e) */

// ---------------- scratch (device globals; no allocations) ----------------
__device__ float g_x  [(size_t)TOK*DIM];     // residual stream fp32
__device__ __nv_bfloat16 g_qkvh[(size_t)TOK*QKVD];
__device__ __nv_bfloat16 g_qkvl[(size_t)TOK*QKVD];
__device__ __nv_bfloat16 g_lnh[(size_t)TOK*DIM];
__device__ __nv_bfloat16 g_lnl[(size_t)TOK*DIM];
__device__ __nv_bfloat16 g_cth[(size_t)TOK*DIM];
__device__ __nv_bfloat16 g_ctl[(size_t)TOK*DIM];
__device__ __nv_bfloat16 g_hh [(size_t)TOK*MLPD];
__device__ __nv_bfloat16 g_hl [(size_t)TOK*MLPD];
// transposed bf16 hi/lo weights [layer][N][K]
__device__ __nv_bfloat16 g_wqkvt_h[(size_t)DEPTH*QKVD*DIM];
__device__ __nv_bfloat16 g_wqkvt_l[(size_t)DEPTH*QKVD*DIM];
__device__ __nv_bfloat16 g_woutt_h[(size_t)DEPTH*DIM*INNER];
__device__ __nv_bfloat16 g_woutt_l[(size_t)DEPTH*DIM*INNER];
__device__ __nv_bfloat16 g_w1t_h [(size_t)DEPTH*MLPD*DIM];
__device__ __nv_bfloat16 g_w1t_l [(size_t)DEPTH*MLPD*DIM];
__device__ __nv_bfloat16 g_w2t_h [(size_t)DEPTH*DIM*MLPD];
__device__ __nv_bfloat16 g_w2t_l [(size_t)DEPTH*DIM*MLPD];

// ====================== PTX helpers =======================================
__device__ __forceinline__ uint32_t smem_u32(const void* p){
    uint32_t a;
    asm("{ .reg .u64 t; cvta.to.shared.u64 t, %1; cvt.u32.u64 %0, t; }"
        : "=r"(a) : "l"(p));
    return a;
}
__device__ __forceinline__ void cp16(uint32_t s, const void* g){
    asm volatile("cp.async.cg.shared.global [%0], [%1], 16;" :: "r"(s), "l"(g));
}
#define CP_COMMIT() asm volatile("cp.async.commit_group;" ::: "memory")
#define CP_WAIT1()  asm volatile("cp.async.wait_group 1;" ::: "memory")
#define CP_WAIT0()  asm volatile("cp.async.wait_group 0;" ::: "memory")

__device__ __forceinline__ void ldmx4(uint32_t addr, uint32_t& r0, uint32_t& r1,
                                      uint32_t& r2, uint32_t& r3){
    asm volatile("ldmatrix.sync.aligned.m8n8.x4.shared.b16 {%0,%1,%2,%3}, [%4];"
        : "=r"(r0), "=r"(r1), "=r"(r2), "=r"(r3) : "r"(addr));
}
__device__ __forceinline__ void ldmx4t(uint32_t addr, uint32_t& r0, uint32_t& r1,
                                       uint32_t& r2, uint32_t& r3){
    asm volatile("ldmatrix.sync.aligned.m8n8.x4.trans.shared.b16 {%0,%1,%2,%3}, [%4];"
        : "=r"(r0), "=r"(r1), "=r"(r2), "=r"(r3) : "r"(addr));
}
__device__ __forceinline__ void mma16816(float* c, const uint32_t* a,
                                         uint32_t b0, uint32_t b1){
    asm volatile(
        "mma.sync.aligned.m16n8k16.row.col.f32.bf16.bf16.f32 "
        "{%0,%1,%2,%3}, {%4,%5,%6,%7}, {%8,%9}, {%0,%1,%2,%3};"
        : "+f"(c[0]), "+f"(c[1]), "+f"(c[2]), "+f"(c[3])
        : "r"(a[0]), "r"(a[1]), "r"(a[2]), "r"(a[3]), "r"(b0), "r"(b1));
}
// FMA-pipe exp2 (degree-6 Taylor on [-0.5,0.5]); valid for t <= 0
__device__ __forceinline__ float exp2_fast(float t){
    t = fmaxf(t, -120.f);
    float n = rintf(t);
    float f = t - n;
    float p = 1.5403530e-4f;
    p = fmaf(p, f, 1.3333558e-3f);
    p = fmaf(p, f, 9.6181291e-3f);
    p = fmaf(p, f, 5.5504109e-2f);
    p = fmaf(p, f, 2.4022651e-1f);
    p = fmaf(p, f, 6.9314718e-1f);
    p = fmaf(p, f, 1.0f);
    return __int_as_float(__float_as_int(p) + (((int)n) << 23));
}

// ====================== weight transpose + bf16 split ======================
__global__ void transpose_cvt(const float* __restrict__ W,
                              __nv_bfloat16* __restrict__ Wh,
                              __nv_bfloat16* __restrict__ Wl, int K, int N)
{
    __shared__ float tile[32][33];
    const size_t off = (size_t)blockIdx.z * K * N;
    const int n0 = blockIdx.x * 32, k0 = blockIdx.y * 32;
    const int tx = threadIdx.x, ty = threadIdx.y;
#pragma unroll
    for (int i = 0; i < 32; i += 8)
        tile[ty + i][tx] = W[off + (size_t)(k0 + ty + i) * N + n0 + tx];
    __syncthreads();
#pragma unroll
    for (int i = 0; i < 32; i += 8) {
        float v = tile[tx][ty + i];
        __nv_bfloat16 h = __float2bfloat16(v);
        __nv_bfloat16 l = __float2bfloat16(v - __bfloat162float(h));
        size_t oidx = off + (size_t)(n0 + ty + i) * K + k0 + tx;
        Wh[oidx] = h; Wl[oidx] = l;
    }
}

// ====================== LayerNorm ==========================================
template<bool BF16OUT>
__global__ void ln_kernel(const float* __restrict__ x, const float* __restrict__ g,
                          const float* __restrict__ b, float* __restrict__ y,
                          __nv_bfloat16* __restrict__ yh, __nv_bfloat16* __restrict__ yl)
{
    int t = blockIdx.x;
    const float* xp = x + (size_t)t * DIM;

    float v[3];
    float s1 = 0.f, s2 = 0.f;
#pragma unroll
    for (int i = 0; i < 3; i++) {
        v[i] = xp[threadIdx.x + i * 256];
        s1 += v[i]; s2 += v[i] * v[i];
    }
#pragma unroll
    for (int o = 16; o > 0; o >>= 1) {
        s1 += __shfl_xor_sync(0xffffffffu, s1, o);
        s2 += __shfl_xor_sync(0xffffffffu, s2, o);
    }
    __shared__ float r1[8], r2[8];
    if ((threadIdx.x & 31) == 0) { r1[threadIdx.x >> 5] = s1; r2[threadIdx.x >> 5] = s2; }
    __syncthreads();
    s1 = 0.f; s2 = 0.f;
#pragma unroll
    for (int i = 0; i < 8; i++) { s1 += r1[i]; s2 += r2[i]; }

    float mu  = s1 * (1.f / DIM);
    float var = s2 * (1.f / DIM) - mu * mu;
    float rs  = rsqrtf(var + 1e-5f);
#pragma unroll
    for (int i = 0; i < 3; i++) {
        int d = threadIdx.x + i * 256;
        float yy = (v[i] - mu) * rs * g[d] + b[d];
        if (BF16OUT) {
            __nv_bfloat16 h = __float2bfloat16(yy);
            yh[(size_t)t * DIM + d] = h;
            yl[(size_t)t * DIM + d] = __float2bfloat16(yy - __bfloat162float(h));
        } else {
            y[(size_t)t * DIM + d] = yy;
        }
    }
}

// ====================== HMMA split-bf16 GEMM ===============================
// EPI: 0 = qkv out (scale Q cols, bf16 hi/lo); 1 = +bias,gelu,bf16 hi/lo;
//      2 = +bias += res; 3 = += res.
template<int EPI>
__global__ void __launch_bounds__(256, 1)
gemm_mma(const __nv_bfloat16* __restrict__ Ah, const __nv_bfloat16* __restrict__ Al,
         const __nv_bfloat16* __restrict__ Bh, const __nv_bfloat16* __restrict__ Bl,
         const float* __restrict__ bias, float* __restrict__ xres,
         __nv_bfloat16* __restrict__ Ch, __nv_bfloat16* __restrict__ Cl,
         int M, int N, int K)
{
    extern __shared__ char smem[];
    const uint32_t sb0 = smem_u32(smem);
    const int tid  = threadIdx.x;
    const int lane = tid & 31, warp = tid >> 5;
    const int wm = warp >> 1, wn = warp & 1;
    const int bn = blockIdx.x, bm = blockIdx.y;
    const int nkt = K >> 5;

    auto load_stage = [&](int kt, int st){
        const uint32_t base = sb0 + st * 32768u;
        const size_t kof = (size_t)kt * 32;
#pragma unroll
        for (int i = 0; i < 2; i++) {
            const int idx = tid + i * 256;
            const int row = idx >> 2, c = idx & 3;
            const uint32_t so = (uint32_t)(row * 64 + ((c ^ ((row >> 1) & 3)) << 4));
            const size_t ga = (size_t)(bm * 128 + row) * K + kof + c * 8;
            const size_t gb = (size_t)(bn * 128 + row) * K + kof + c * 8;
            cp16(base + so,          Ah + ga);
            cp16(base + 8192u + so,  Al + ga);
            cp16(base + 16384u + so, Bh + gb);
            cp16(base + 24576u + so, Bl + gb);
        }
    };

    float acc[2][8][4];
#pragma unroll
    for (int mt = 0; mt < 2; mt++)
#pragma unroll
        for (int nt = 0; nt < 8; nt++)
#pragma unroll
            for (int q = 0; q < 4; q++) acc[mt][nt][q] = 0.f;

    load_stage(0, 0); CP_COMMIT();
    load_stage(1, 1); CP_COMMIT();

    const int arow = wm * 32 + (lane & 15);
    const int acs  = lane >> 4;
    const int brow = wn * 64 + (lane & 7) + ((lane >> 4) << 3);
    const int bcs  = (lane >> 3) & 1;

    for (int kt = 0; kt < nkt; kt++) {
        if (kt == nkt - 1) { CP_WAIT0(); } else { CP_WAIT1(); }
        __syncthreads();
        if (kt + 2 < nkt) { load_stage(kt + 2, (kt + 2) % 3); CP_COMMIT(); }

        const uint32_t base = sb0 + (uint32_t)(kt % 3) * 32768u;
#pragma unroll
        for (int ks = 0; ks < 2; ks++) {
            uint32_t ah[2][4], al_[2][4];
#pragma unroll
            for (int mt = 0; mt < 2; mt++) {
                const int r = arow + mt * 16;
                const int c = ks * 2 + acs;
                const uint32_t off = (uint32_t)(r * 64 + ((c ^ ((r >> 1) & 3)) << 4));
                ldmx4(base + off,         ah[mt][0],  ah[mt][1],  ah[mt][2],  ah[mt][3]);
                ldmx4(base + 8192u + off, al_[mt][0], al_[mt][1], al_[mt][2], al_[mt][3]);
            }
            uint32_t bh[4][4], bl_[4][4];
#pragma unroll
            for (int bt = 0; bt < 4; bt++) {
                const int r = brow + bt * 16;
                const int c = ks * 2 + bcs;
                const uint32_t off = (uint32_t)(r * 64 + ((c ^ ((r >> 1) & 3)) << 4));
                ldmx4(base + 16384u + off, bh[bt][0],  bh[bt][1],  bh[bt][2],  bh[bt][3]);
                ldmx4(base + 24576u + off, bl_[bt][0], bl_[bt][1], bl_[bt][2], bl_[bt][3]);
            }
#pragma unroll
            for (int mt = 0; mt < 2; mt++)
#pragma unroll
                for (int nt = 0; nt < 8; nt++) {
                    const int bt = nt >> 1, o = (nt & 1) * 2;
                    mma16816(acc[mt][nt], ah[mt],  bh[bt][o],  bh[bt][o + 1]);
                    mma16816(acc[mt][nt], ah[mt],  bl_[bt][o], bl_[bt][o + 1]);
                    mma16816(acc[mt][nt], al_[mt], bh[bt][o],  bh[bt][o + 1]);
                }
        }
        __syncthreads();
    }

    const int rbase = bm * 128 + wm * 32 + (lane >> 2);
    const int cbase = bn * 128 + wn * 64 + (lane & 3) * 2;
#pragma unroll
    for (int mt = 0; mt < 2; mt++) {
#pragma unroll
        for (int nt = 0; nt < 8; nt++) {
            const int gcol = cbase + nt * 8;
#pragma unroll
            for (int h = 0; h < 2; h++) {
                const int grow = rbase + mt * 16 + h * 8;
                float v0 = acc[mt][nt][2 * h], v1 = acc[mt][nt][2 * h + 1];
                const size_t oidx = (size_t)grow * N + gcol;
                if (EPI == 0 || EPI == 1) {
                    if (EPI == 0) {
                        const float sc = (gcol < INNER) ? QSCALE : 1.f;
                        v0 *= sc; v1 *= sc;
                    } else {
                        v0 += bias[gcol];     v1 += bias[gcol + 1];
                        v0 = 0.5f * v0 * (1.f + erff(v0 * 0.70710678118654752f));
                        v1 = 0.5f * v1 * (1.f + erff(v1 * 0.70710678118654752f));
                    }
                    __nv_bfloat16 h0 = __float2bfloat16(v0), h1 = __float2bfloat16(v1);
                    __nv_bfloat16 l0 = __float2bfloat16(v0 - __bfloat162float(h0));
                    __nv_bfloat16 l1 = __float2bfloat16(v1 - __bfloat162float(h1));
                    *reinterpret_cast<uint32_t*>(Ch + oidx) =
                        (uint32_t)__bfloat16_as_ushort(h0) |
                        ((uint32_t)__bfloat16_as_ushort(h1) << 16);
                    *reinterpret_cast<uint32_t*>(Cl + oidx) =
                        (uint32_t)__bfloat16_as_ushort(l0) |
                        ((uint32_t)__bfloat16_as_ushort(l1) << 16);
                } else {
                    float2 xv = *reinterpret_cast<const float2*>(xres + oidx);
                    if (EPI == 2) { v0 += bias[gcol]; v1 += bias[gcol + 1]; }
                    xv.x += v0; xv.y += v1;
                    *reinterpret_cast<float2*>(xres + oidx) = xv;
                }
            }
        }
    }
}

// ====================== HMMA flash attention ===============================
// grid (SEQ/128, HEADS, BATCH), 256 threads (8 warps x 16 query rows).
// qkv hi/lo bf16 in [tok][2304]; Q pre-scaled by 0.125*log2e.
#define ATTN_SMEM (32768 + 2*32768)
__global__ void __launch_bounds__(256, 1)
attn_mma(const __nv_bfloat16* __restrict__ qg_h, const __nv_bfloat16* __restrict__ qg_l,
         __nv_bfloat16* __restrict__ ch, __nv_bfloat16* __restrict__ cl)
{
    extern __shared__ char smem[];
    const uint32_t sb = smem_u32(smem);
    const uint32_t QH = sb, QL = sb + 16384u;
    const int tid = threadIdx.x, lane = tid & 31, wid = tid >> 5;
    const int b = blockIdx.z, h = blockIdx.y, qt = blockIdx.x;
    const int tok0 = b * SEQ + qt * 128;

    // ---- load Q tile (hi/lo), swizzled 128B rows ----
#pragma unroll
    for (int i = 0; i < 4; i++) {
        const int idx = tid + i * 256;
        const int row = idx >> 3, c = idx & 7;
        const uint32_t so = (uint32_t)(row * 128 + ((c ^ (row & 7)) << 4));
        const size_t g = (size_t)(tok0 + row) * QKVD + h * DHEAD + c * 8;
        cp16(QH + so, qg_h + g);
        cp16(QL + so, qg_l + g);
    }

    auto load_kv = [&](int t, int st){
        const uint32_t base = sb + 32768u + (uint32_t)st * 32768u;
        const int kv0 = b * SEQ + t * 64;
#pragma unroll
        for (int i = 0; i < 2; i++) {
            const int idx = tid + i * 256;
            const int row = idx >> 3, c = idx & 7;
            const uint32_t so = (uint32_t)(row * 128 + ((c ^ (row & 7)) << 4));
            const size_t gk = (size_t)(kv0 + row) * QKVD + INNER + h * DHEAD + c * 8;
            const size_t gv = (size_t)(kv0 + row) * QKVD + 2 * INNER + h * DHEAD + c * 8;
            cp16(base + so,          qg_h + gk);
            cp16(base + 8192u  + so, qg_l + gk);
            cp16(base + 16384u + so, qg_h + gv);
            cp16(base + 24576u + so, qg_l + gv);
        }
    };
    load_kv(0, 0); CP_COMMIT();

    float O[8][4];
#pragma unroll
    for (int nt = 0; nt < 8; nt++)
#pragma unroll
        for (int q = 0; q < 4; q++) O[nt][q] = 0.f;
    float m0 = -1e30f, m1 = -1e30f, l0 = 0.f, l1 = 0.f;
    const int m0row = wid * 16;

    const int NT = SEQ / 64;
    for (int t = 0; t < NT; t++) {
        if (t + 1 < NT) { load_kv(t + 1, (t + 1) & 1); CP_COMMIT(); CP_WAIT1(); }
        else            { CP_WAIT0(); }
        __syncthreads();
        const uint32_t kb = sb + 32768u + (uint32_t)(t & 1) * 32768u;

        // ---- S = Q @ K^T (3 split products) ----
        float S[8][4];
#pragma unroll
        for (int nt = 0; nt < 8; nt++)
#pragma unroll
            for (int q = 0; q < 4; q++) S[nt][q] = 0.f;
#pragma unroll
        for (int ks = 0; ks < 4; ks++) {
            uint32_t ah[4], al_[4];
            {
                const int r = m0row + (lane & 15);
                const int c = ks * 2 + (lane >> 4);
                const uint32_t off = (uint32_t)(r * 128 + ((c ^ (r & 7)) << 4));
                ldmx4(QH + off, ah[0], ah[1], ah[2], ah[3]);
                ldmx4(QL + off, al_[0], al_[1], al_[2], al_[3]);
            }
#pragma unroll
            for (int bt = 0; bt < 4; bt++) {
                const int r = bt * 16 + (lane & 7) + ((lane >> 4) << 3);
                const int c = ks * 2 + ((lane >> 3) & 1);
                const uint32_t off = (uint32_t)(r * 128 + ((c ^ (r & 7)) << 4));
                uint32_t kh[4], kl[4];
                ldmx4(kb + off,         kh[0], kh[1], kh[2], kh[3]);
                ldmx4(kb + 8192u + off, kl[0], kl[1], kl[2], kl[3]);
                mma16816(S[2*bt],   ah,  kh[0], kh[1]);
                mma16816(S[2*bt],   ah,  kl[0], kl[1]);
                mma16816(S[2*bt],   al_, kh[0], kh[1]);
                mma16816(S[2*bt+1], ah,  kh[2], kh[3]);
                mma16816(S[2*bt+1], ah,  kl[2], kl[3]);
                mma16816(S[2*bt+1], al_, kh[2], kh[3]);
            }
        }

        // ---- online softmax (base-2 domain) ----
        float mt0 = -1e30f, mt1 = -1e30f;
#pragma unroll
        for (int nt = 0; nt < 8; nt++) {
            mt0 = fmaxf(mt0, fmaxf(S[nt][0], S[nt][1]));
            mt1 = fmaxf(mt1, fmaxf(S[nt][2], S[nt][3]));
        }
        mt0 = fmaxf(mt0, __shfl_xor_sync(0xffffffffu, mt0, 1));
        mt0 = fmaxf(mt0, __shfl_xor_sync(0xffffffffu, mt0, 2));
        mt1 = fmaxf(mt1, __shfl_xor_sync(0xffffffffu, mt1, 1));
        mt1 = fmaxf(mt1, __shfl_xor_sync(0xffffffffu, mt1, 2));
        const float mn0 = fmaxf(m0, mt0), mn1 = fmaxf(m1, mt1);
        const float cr0 = exp2_fast(m0 - mn0), cr1 = exp2_fast(m1 - mn1);
        m0 = mn0; m1 = mn1;

        uint32_t phi[4][4], plo[4][4];
        float s0 = 0.f, s1 = 0.f;
#pragma unroll
        for (int nt = 0; nt < 8; nt++) {
            float p0 = exp2_fast(S[nt][0] - m0);
            float p1 = exp2_fast(S[nt][1] - m0);
            float p2 = exp2_fast(S[nt][2] - m1);
            float p3 = exp2_fast(S[nt][3] - m1);
            s0 += p0 + p1; s1 += p2 + p3;
            __nv_bfloat16 h0 = __float2bfloat16(p0), h1 = __float2bfloat16(p1);
            __nv_bfloat16 h2 = __float2bfloat16(p2), h3 = __float2bfloat16(p3);
            const int t2 = nt >> 1, o = (nt & 1) * 2;
            phi[t2][o] = (uint32_t)__bfloat16_as_ushort(h0) |
                         ((uint32_t)__bfloat16_as_ushort(h1) << 16);
            phi[t2][o+1] = (uint32_t)__bfloat16_as_ushort(h2) |
                           ((uint32_t)__bfloat16_as_ushort(h3) << 16);
            __nv_bfloat16 e0 = __float2bfloat16(p0 - __bfloat162float(h0));
            __nv_bfloat16 e1 = __float2bfloat16(p1 - __bfloat162float(h1));
            __nv_bfloat16 e2 = __float2bfloat16(p2 - __bfloat162float(h2));
            __nv_bfloat16 e3 = __float2bfloat16(p3 - __bfloat162float(h3));
            plo[t2][o] = (uint32_t)__bfloat16_as_ushort(e0) |
                         ((uint32_t)__bfloat16_as_ushort(e1) << 16);
            plo[t2][o+1] = (uint32_t)__bfloat16_as_ushort(e2) |
                           ((uint32_t)__bfloat16_as_ushort(e3) << 16);
        }
        s0 += __shfl_xor_sync(0xffffffffu, s0, 1);
        s0 += __shfl_xor_sync(0xffffffffu, s0, 2);
        s1 += __shfl_xor_sync(0xffffffffu, s1, 1);
        s1 += __shfl_xor_sync(0xffffffffu, s1, 2);
        l0 = l0 * cr0 + s0;
        l1 = l1 * cr1 + s1;
#pragma unroll
        for (int nt = 0; nt < 8; nt++) {
            O[nt][0] *= cr0; O[nt][1] *= cr0;
            O[nt][2] *= cr1; O[nt][3] *= cr1;
        }

        // ---- O += P @ V (3 split products) ----
#pragma unroll
        for (int t2 = 0; t2 < 4; t2++) {
#pragma unroll
            for (int dn = 0; dn < 4; dn++) {
                const int r = t2 * 16 + (lane & 15);
                const int c = dn * 2 + (lane >> 4);
                const uint32_t off = (uint32_t)(r * 128 + ((c ^ (r & 7)) << 4));
                uint32_t vh[4], vl[4];
                ldmx4t(kb + 16384u + off, vh[0], vh[1], vh[2], vh[3]);
                ldmx4t(kb + 24576u + off, vl[0], vl[1], vl[2], vl[3]);
                mma16816(O[2*dn],   phi[t2], vh[0], vh[1]);
                mma16816(O[2*dn],   plo[t2], vh[0], vh[1]);
                mma16816(O[2*dn],   phi[t2], vl[0], vl[1]);
                mma16816(O[2*dn+1], phi[t2], vh[2], vh[3]);
                mma16816(O[2*dn+1], plo[t2], vh[2], vh[3]);
                mma16816(O[2*dn+1], phi[t2], vl[2], vl[3]);
            }
        }
        __syncthreads();
    }

    // ---- epilogue: normalize, split hi/lo, store ctx ----
    const float i0 = 1.f / l0, i1 = 1.f / l1;
    const int r0 = tok0 + m0row + (lane >> 2);
#pragma unroll
    for (int nt = 0; nt < 8; nt++) {
        const int col = h * DHEAD + nt * 8 + (lane & 3) * 2;
#pragma unroll
        for (int hh = 0; hh < 2; hh++) {
            const float inv = hh ? i1 : i0;
            float v0 = O[nt][2*hh] * inv, v1 = O[nt][2*hh+1] * inv;
            __nv_bfloat16 h0 = __float2bfloat16(v0), h1 = __float2bfloat16(v1);
            __nv_bfloat16 e0 = __float2bfloat16(v0 - __bfloat162float(h0));
            __nv_bfloat16 e1 = __float2bfloat16(v1 - __bfloat162float(h1));
            const size_t oidx = (size_t)(r0 + hh * 8) * DIM + col;
            *reinterpret_cast<uint32_t*>(ch + oidx) =
                (uint32_t)__bfloat16_as_ushort(h0) |
                ((uint32_t)__bfloat16_as_ushort(h1) << 16);
            *reinterpret_cast<uint32_t*>(cl + oidx) =
                (uint32_t)__bfloat16_as_ushort(e0) |
                ((uint32_t)__bfloat16_as_ushort(e1) << 16);
        }
    }
}

// ====================== driver =============================================
#define GEMM_SMEM (3 * 32768)

extern "C" void kernel_launch(void* const* d_in, const int* in_sizes, int n_in,
                              void* d_out, int out_size)
{
    const float* x    = (const float*)d_in[0];
    const float* ln1g = (const float*)d_in[1];
    const float* ln1b = (const float*)d_in[2];
    const float* wqkv = (const float*)d_in[3];
    const float* wout = (const float*)d_in[4];
    const float* ln2g = (const float*)d_in[5];
    const float* ln2b = (const float*)d_in[6];
    const float* w1   = (const float*)d_in[7];
    const float* b1   = (const float*)d_in[8];
    const float* w2   = (const float*)d_in[9];
    const float* b2   = (const float*)d_in[10];
    const float* fng  = (const float*)d_in[11];
    const float* fnb  = (const float*)d_in[12];

    float *px;
    __nv_bfloat16 *pqh, *pql, *plnh, *plnl, *pcth, *pctl, *phh, *phl;
    __nv_bfloat16 *qkvh, *qkvl, *outh, *outl, *w1h, *w1l, *w2h, *w2l;
    cudaGetSymbolAddress((void**)&px,   g_x);
    cudaGetSymbolAddress((void**)&pqh,  g_qkvh);
    cudaGetSymbolAddress((void**)&pql,  g_qkvl);
    cudaGetSymbolAddress((void**)&plnh, g_lnh);
    cudaGetSymbolAddress((void**)&plnl, g_lnl);
    cudaGetSymbolAddress((void**)&pcth, g_cth);
    cudaGetSymbolAddress((void**)&pctl, g_ctl);
    cudaGetSymbolAddress((void**)&phh,  g_hh);
    cudaGetSymbolAddress((void**)&phl,  g_hl);
    cudaGetSymbolAddress((void**)&qkvh, g_wqkvt_h);
    cudaGetSymbolAddress((void**)&qkvl, g_wqkvt_l);
    cudaGetSymbolAddress((void**)&outh, g_woutt_h);
    cudaGetSymbolAddress((void**)&outl, g_woutt_l);
    cudaGetSymbolAddress((void**)&w1h,  g_w1t_h);
    cudaGetSymbolAddress((void**)&w1l,  g_w1t_l);
    cudaGetSymbolAddress((void**)&w2h,  g_w2t_h);
    cudaGetSymbolAddress((void**)&w2l,  g_w2t_l);

    cudaFuncSetAttribute(gemm_mma<0>, cudaFuncAttributeMaxDynamicSharedMemorySize, GEMM_SMEM);
    cudaFuncSetAttribute(gemm_mma<1>, cudaFuncAttributeMaxDynamicSharedMemorySize, GEMM_SMEM);
    cudaFuncSetAttribute(gemm_mma<2>, cudaFuncAttributeMaxDynamicSharedMemorySize, GEMM_SMEM);
    cudaFuncSetAttribute(gemm_mma<3>, cudaFuncAttributeMaxDynamicSharedMemorySize, GEMM_SMEM);
    cudaFuncSetAttribute(attn_mma, cudaFuncAttributeMaxDynamicSharedMemorySize, ATTN_SMEM);

    {
        dim3 tblk(32, 8);
        transpose_cvt<<<dim3(QKVD/32, DIM/32, DEPTH), tblk>>>(wqkv, qkvh, qkvl, DIM, QKVD);
        transpose_cvt<<<dim3(DIM/32, INNER/32, DEPTH), tblk>>>(wout, outh, outl, INNER, DIM);
        transpose_cvt<<<dim3(MLPD/32, DIM/32, DEPTH), tblk>>>(w1, w1h, w1l, DIM, MLPD);
        transpose_cvt<<<dim3(DIM/32, MLPD/32, DEPTH), tblk>>>(w2, w2h, w2l, MLPD, DIM);
    }

    cudaMemcpyAsync(px, x, sizeof(float) * (size_t)TOK * DIM,
                    cudaMemcpyDeviceToDevice, 0);

    const dim3 blk256(256);
    for (int i = 0; i < DEPTH; i++) {
        ln_kernel<true><<<TOK, blk256>>>(px, ln1g + i*DIM, ln1b + i*DIM,
                                         nullptr, plnh, plnl);
        gemm_mma<0><<<dim3(QKVD/128, TOK/128), blk256, GEMM_SMEM>>>(
            plnh, plnl,
            qkvh + (size_t)i*QKVD*DIM, qkvl + (size_t)i*QKVD*DIM,
            nullptr, nullptr, pqh, pql, TOK, QKVD, DIM);
        attn_mma<<<dim3(SEQ/128, HEADS, BATCH), blk256, ATTN_SMEM>>>(pqh, pql, pcth, pctl);
        gemm_mma<3><<<dim3(DIM/128, TOK/128), blk256, GEMM_SMEM>>>(
            pcth, pctl,
            outh + (size_t)i*DIM*INNER, outl + (size_t)i*DIM*INNER,
            nullptr, px, nullptr, nullptr, TOK, DIM, INNER);

        ln_kernel<true><<<TOK, blk256>>>(px, ln2g + i*DIM, ln2b + i*DIM,
                                         nullptr, plnh, plnl);
        gemm_mma<1><<<dim3(MLPD/128, TOK/128), blk256, GEMM_SMEM>>>(
            plnh, plnl,
            w1h + (size_t)i*MLPD*DIM, w1l + (size_t)i*MLPD*DIM,
            b1 + (size_t)i*MLPD, nullptr, phh, phl, TOK, MLPD, DIM);
        gemm_mma<2><<<dim3(DIM/128, TOK/128), blk256, GEMM_SMEM>>>(
            phh, phl,
            w2h + (size_t)i*DIM*MLPD, w2l + (size_t)i*DIM*MLPD,
            b2 + (size_t)i*DIM, px, nullptr, nullptr, TOK, DIM, MLPD);
    }

    ln_kernel<false><<<TOK, blk256>>>(px, fng, fnb, (float*)d_out, nullptr, nullptr);
}